// round 1
// baseline (speedup 1.0000x reference)
#include <cuda_runtime.h>
#include <cuda_bf16.h>
#include <math.h>

// Problem constants
#define BB    8
#define CIN   64
#define HH    128
#define WW    128
#define COUT  128
#define KK9   9
#define NPIX  (HH*WW)           // 16384
#define KTOT  (KK9*CIN)         // 576

// Scratch (allocation-free rule: __device__ globals)
__device__ float g_x2[BB*NPIX*CIN];        // NHWC: [b][h][w][c]   33.5 MB
__device__ float g_offm[BB*NPIX*32];       // per-pixel [32]: 0..17 offsets, 18..26 mask, 27..31 pad
__device__ float g_wt[KTOT*COUT];          // transposed reg_w: [k = kk*64 + c][o]

// ---------------------------------------------------------------------------
// K0: transpose reg_w[o][c][kk] -> g_wt[kk*64+c][o]
// ---------------------------------------------------------------------------
__global__ void k0_wt(const float* __restrict__ rw) {
    int i = blockIdx.x * 256 + threadIdx.x;
    if (i < KTOT * COUT) {
        int o = i & 127;
        int k = i >> 7;
        int kk = k >> 6;       // k = kk*64 + c
        int c  = k & 63;
        g_wt[i] = rw[(o * 64 + c) * 9 + kk];
    }
}

// ---------------------------------------------------------------------------
// K1: 1x1 pre-conv, NCHW in -> NHWC out (g_x2)
// block = one (b,h) row, 128 threads = 128 w-pixels
// ---------------------------------------------------------------------------
__global__ void __launch_bounds__(128) k1_pre(const float* __restrict__ x,
                                              const float* __restrict__ pre_w,
                                              const float* __restrict__ pre_b) {
    __shared__ float wsm[64 * 64];   // [ci][co]
    __shared__ float bsm[64];
    int tid = threadIdx.x;
    for (int i = tid; i < 4096; i += 128) {
        int co = i & 63, ci = i >> 6;
        wsm[ci * 64 + co] = pre_w[co * 64 + ci];
    }
    if (tid < 64) bsm[tid] = pre_b[tid];
    __syncthreads();

    int bh = blockIdx.x;             // b*128 + h
    int b = bh >> 7, h = bh & 127;
    int w = tid;

    const float* xp = x + (size_t)b * 64 * NPIX + h * WW + w;
    float xin[64];
#pragma unroll
    for (int ci = 0; ci < 64; ci++) xin[ci] = xp[(size_t)ci * NPIX];

    float4* out4 = (float4*)(g_x2 + ((size_t)bh * WW + w) * 64);
    const float4* wsm4 = (const float4*)wsm;
    const float4* b4 = (const float4*)bsm;
#pragma unroll
    for (int cog = 0; cog < 16; cog++) {
        float4 acc = b4[cog];
#pragma unroll
        for (int ci = 0; ci < 64; ci++) {
            float4 wv = wsm4[ci * 16 + cog];
            acc.x += xin[ci] * wv.x;
            acc.y += xin[ci] * wv.y;
            acc.z += xin[ci] * wv.z;
            acc.w += xin[ci] * wv.w;
        }
        out4[cog] = acc;
    }
}

// ---------------------------------------------------------------------------
// K2: fused offset (18ch) + mask (9ch) 3x3 conv on NHWC x2.
// block = 32 pixels of one row. 256 threads: co = tid&31, pixgroup = tid>>5 (4 px each).
// outputs interleaved per-pixel: g_offm[pix][32]
// dynamic smem: xs[3*34*64] + wsm[576*32]
// ---------------------------------------------------------------------------
extern __shared__ float dyn_smem[];

__global__ void __launch_bounds__(256) k2_offmask(const float* __restrict__ off_w,
                                                  const float* __restrict__ off_b,
                                                  const float* __restrict__ mod_w,
                                                  const float* __restrict__ mod_b) {
    float* xs  = dyn_smem;            // 3*34*64 = 6528
    float* wsm = dyn_smem + 6528;     // 576*32 = 18432

    int tid = threadIdx.x;
    int bx = blockIdx.x;
    int seg = bx & 3, h = (bx >> 2) & 127, b = bx >> 9;
    int w0 = seg * 32;

    // load input tile (rows h-1..h+1, cols w0-1..w0+32), zero-padded
    for (int i = tid; i < 3 * 34 * 64; i += 256) {
        int c = i & 63;
        int t2 = i >> 6;
        int cc = t2 % 34;
        int r = t2 / 34;
        int y = h - 1 + r;
        int xg = w0 - 1 + cc;
        float v = 0.f;
        if ((unsigned)y < 128u && (unsigned)xg < 128u)
            v = g_x2[(((size_t)(b * 128 + y)) * 128 + xg) * 64 + c];
        xs[i] = v;
    }
    // load weights transposed: wsm[k*32 + co], k = ci*9 + ky*3 + kx
    for (int i = tid; i < 576 * 32; i += 256) {
        int co = i & 31;
        int k = i >> 5;
        float v = 0.f;
        if (co < 18)      v = off_w[co * 576 + k];
        else if (co < 27) v = mod_w[(co - 18) * 576 + k];
        wsm[i] = v;
    }
    __syncthreads();

    int co = tid & 31;
    int pg = tid >> 5;           // 0..7
    int px0 = pg * 4;

    float acc0 = 0.f, acc1 = 0.f, acc2 = 0.f, acc3 = 0.f;
#pragma unroll 4
    for (int ci = 0; ci < 64; ci++) {
#pragma unroll
        for (int ky = 0; ky < 3; ky++) {
#pragma unroll
            for (int kx = 0; kx < 3; kx++) {
                float wv = wsm[((ci * 9 + ky * 3 + kx) << 5) + co];
                const float* xrow = xs + (ky * 34 + px0 + kx) * 64 + ci;
                acc0 += wv * xrow[0];
                acc1 += wv * xrow[64];
                acc2 += wv * xrow[128];
                acc3 += wv * xrow[192];
            }
        }
    }

    float bias = 0.f;
    if (co < 18)      bias = off_b[co];
    else if (co < 27) bias = mod_b[co - 18];
    float vals[4] = {acc0 + bias, acc1 + bias, acc2 + bias, acc3 + bias};

    size_t pixbase = ((size_t)(b * 128 + h)) * 128 + w0 + px0;
    bool is_mask = (co >= 18 && co < 27);
#pragma unroll
    for (int j = 0; j < 4; j++) {
        float v = vals[j];
        if (is_mask) v = 2.0f / (1.0f + expf(-v));
        g_offm[(pixbase + j) * 32 + co] = v;
    }
}

// ---------------------------------------------------------------------------
// K3: deformable sampling + modulation + contraction.
// block = 32 pixels of one row. 256 threads.
// Phase 1: warp-per-kk builds s[k = kk*64+c][pix] in smem (lane = pixel; conflict-free STS,
//          float4 channel gathers from NHWC x2).
// Phase 2: out[o][pix] = sum_k g_wt[k][o] * s[k][pix]; thread = (2 outputs) x (8 pixels).
// dynamic smem: s[576*32] + osm[32*32]
// ---------------------------------------------------------------------------
__global__ void __launch_bounds__(256, 2) k3_main(float* __restrict__ out) {
    float* s   = dyn_smem;            // 18432
    float* osm = dyn_smem + 18432;    // 1024

    int tid = threadIdx.x;
    int bx = blockIdx.x;
    int seg = bx & 3, h = (bx >> 2) & 127, b = bx >> 9;
    int w0 = seg * 32;
    size_t pixbase = ((size_t)(b * 128 + h)) * 128 + w0;

    for (int i = tid; i < 1024; i += 256)
        osm[i] = g_offm[pixbase * 32 + i];
    __syncthreads();

    int warp = tid >> 5, lane = tid & 31;

    // -------- phase 1: build sample matrix --------
    for (int kk = warp; kk < 9; kk += 8) {
        int ky = kk / 3, kx = kk - ky * 3;
        float dy = osm[lane * 32 + 2 * kk];
        float dx = osm[lane * 32 + 2 * kk + 1];
        float m  = osm[lane * 32 + 18 + kk];

        float py  = (float)(h - 1 + ky) + dy;
        float pxf = (float)(w0 + lane - 1 + kx) + dx;
        float y0f = floorf(py), x0f = floorf(pxf);
        float wy = py - y0f, wx = pxf - x0f;
        int y0 = (int)y0f, x0 = (int)x0f;
        int y1 = y0 + 1,  x1 = x0 + 1;

        float w00 = (1.f - wy) * (1.f - wx) * m;
        float w01 = (1.f - wy) * wx * m;
        float w10 = wy * (1.f - wx) * m;
        float w11 = wy * wx * m;
        if ((unsigned)y0 >= 128u) { w00 = 0.f; w01 = 0.f; }
        if ((unsigned)y1 >= 128u) { w10 = 0.f; w11 = 0.f; }
        if ((unsigned)x0 >= 128u) { w00 = 0.f; w10 = 0.f; }
        if ((unsigned)x1 >= 128u) { w01 = 0.f; w11 = 0.f; }

        int yc0 = min(max(y0, 0), 127), yc1 = min(max(y1, 0), 127);
        int xc0 = min(max(x0, 0), 127), xc1 = min(max(x1, 0), 127);

        size_t rb = (size_t)(b * 128);
        const float4* p00 = (const float4*)(g_x2 + ((rb + yc0) * 128 + xc0) * 64);
        const float4* p01 = (const float4*)(g_x2 + ((rb + yc0) * 128 + xc1) * 64);
        const float4* p10 = (const float4*)(g_x2 + ((rb + yc1) * 128 + xc0) * 64);
        const float4* p11 = (const float4*)(g_x2 + ((rb + yc1) * 128 + xc1) * 64);

        float* sdst = s + kk * 64 * 32 + lane;   // s[(kk*64+c)*32 + pix]
#pragma unroll
        for (int c4 = 0; c4 < 16; c4++) {
            float4 a = p00[c4], bb = p01[c4], cc = p10[c4], dd = p11[c4];
            sdst[(c4 * 4 + 0) * 32] = w00 * a.x + w01 * bb.x + w10 * cc.x + w11 * dd.x;
            sdst[(c4 * 4 + 1) * 32] = w00 * a.y + w01 * bb.y + w10 * cc.y + w11 * dd.y;
            sdst[(c4 * 4 + 2) * 32] = w00 * a.z + w01 * bb.z + w10 * cc.z + w11 * dd.z;
            sdst[(c4 * 4 + 3) * 32] = w00 * a.w + w01 * bb.w + w10 * cc.w + w11 * dd.w;
        }
    }
    __syncthreads();

    // -------- phase 2: GEMM 128 x 576 x 32 --------
    int og = tid & 63;         // output pair index: o = 2*og
    int half = tid >> 6;       // 0..3 -> pixels half*8 .. half*8+7
    int o = og * 2;

    float acc[2][8];
#pragma unroll
    for (int i = 0; i < 2; i++)
#pragma unroll
        for (int j = 0; j < 8; j++) acc[i][j] = 0.f;

    const float4* s4 = (const float4*)s;
    const float2* wt2 = (const float2*)g_wt;   // [k*64 + og]

#pragma unroll 4
    for (int k = 0; k < KTOT; k++) {
        float2 wv = wt2[k * 64 + og];
        float4 sa = s4[k * 8 + half * 2];
        float4 sb = s4[k * 8 + half * 2 + 1];
        acc[0][0] += wv.x * sa.x;  acc[0][1] += wv.x * sa.y;
        acc[0][2] += wv.x * sa.z;  acc[0][3] += wv.x * sa.w;
        acc[0][4] += wv.x * sb.x;  acc[0][5] += wv.x * sb.y;
        acc[0][6] += wv.x * sb.z;  acc[0][7] += wv.x * sb.w;
        acc[1][0] += wv.y * sa.x;  acc[1][1] += wv.y * sa.y;
        acc[1][2] += wv.y * sa.z;  acc[1][3] += wv.y * sa.w;
        acc[1][4] += wv.y * sb.x;  acc[1][5] += wv.y * sb.y;
        acc[1][6] += wv.y * sb.z;  acc[1][7] += wv.y * sb.w;
    }

#pragma unroll
    for (int i = 0; i < 2; i++) {
        float* op = out + ((size_t)(b * COUT + o + i)) * NPIX + h * WW + w0 + half * 8;
        float4 v0 = make_float4(acc[i][0], acc[i][1], acc[i][2], acc[i][3]);
        float4 v1 = make_float4(acc[i][4], acc[i][5], acc[i][6], acc[i][7]);
        *(float4*)op = v0;
        *(float4*)(op + 4) = v1;
    }
}

// ---------------------------------------------------------------------------
extern "C" void kernel_launch(void* const* d_in, const int* in_sizes, int n_in,
                              void* d_out, int out_size) {
    const float* x     = (const float*)d_in[0];
    const float* pre_w = (const float*)d_in[1];
    const float* pre_b = (const float*)d_in[2];
    const float* off_w = (const float*)d_in[3];
    const float* off_b = (const float*)d_in[4];
    const float* mod_w = (const float*)d_in[5];
    const float* mod_b = (const float*)d_in[6];
    const float* reg_w = (const float*)d_in[7];
    float* out = (float*)d_out;

    const int K2_SMEM = (6528 + 18432) * 4;        // 99840 B
    const int K3_SMEM = (18432 + 1024) * 4;        // 77824 B
    cudaFuncSetAttribute(k2_offmask, cudaFuncAttributeMaxDynamicSharedMemorySize, K2_SMEM);
    cudaFuncSetAttribute(k3_main, cudaFuncAttributeMaxDynamicSharedMemorySize, K3_SMEM);

    k0_wt<<<(KTOT * COUT + 255) / 256, 256>>>(reg_w);
    k1_pre<<<BB * HH, 128>>>(x, pre_w, pre_b);
    k2_offmask<<<BB * HH * (WW / 32), 256, K2_SMEM>>>(off_w, off_b, mod_w, mod_b);
    k3_main<<<BB * HH * (WW / 32), 256, K3_SMEM>>>(out);
}

// round 2
// speedup vs baseline: 2.0059x; 2.0059x over previous
#include <cuda_runtime.h>
#include <cuda_bf16.h>
#include <math.h>

#define BB    8
#define CIN   64
#define HH    128
#define WW    128
#define COUT  128
#define NPIX  (HH*WW)           // 16384
#define KTOT  (9*CIN)           // 576

// Scratch (__device__ globals; no allocation)
__device__ float g_x2 [BB*NPIX*CIN];   // NHWC: [b][h][w][c]
__device__ float g_x2t[BB*NPIX*CIN];   // NCHW: [b][c][h][w]
__device__ float g_offm[BB*NPIX*32];   // per-pixel [32]: 0..17 off, 18..26 mask
__device__ float g_wt[KTOT*COUT];      // [kk*64+c][o]
__device__ float g_w2[KTOT*32];        // k2 weights padded: [ci*9+kk][co(32)]

// ---------------------------------------------------------------------------
// K0: weight prep
// ---------------------------------------------------------------------------
__global__ void k0_wt(const float* __restrict__ rw,
                      const float* __restrict__ off_w,
                      const float* __restrict__ mod_w) {
    int i = blockIdx.x * 256 + threadIdx.x;
    if (i < KTOT * COUT) {
        int o = i & 127, k = i >> 7;
        int kk = k >> 6, c = k & 63;
        g_wt[i] = rw[(o * 64 + c) * 9 + kk];
    }
    if (i < KTOT * 32) {
        int co = i & 31, k = i >> 5;   // k = ci*9 + kk
        float v = 0.f;
        if (co < 18)      v = off_w[co * 576 + k];
        else if (co < 27) v = mod_w[(co - 18) * 576 + k];
        g_w2[i] = v;
    }
}

// ---------------------------------------------------------------------------
// K1: 1x1 pre-conv, NCHW in -> NHWC (g_x2) + NCHW (g_x2t)
// ---------------------------------------------------------------------------
__global__ void __launch_bounds__(128) k1_pre(const float* __restrict__ x,
                                              const float* __restrict__ pre_w,
                                              const float* __restrict__ pre_b) {
    __shared__ float wsm[64 * 64];   // [ci][co]
    __shared__ float bsm[64];
    int tid = threadIdx.x;
    for (int i = tid; i < 4096; i += 128) {
        int co = i & 63, ci = i >> 6;
        wsm[ci * 64 + co] = pre_w[co * 64 + ci];
    }
    if (tid < 64) bsm[tid] = pre_b[tid];
    __syncthreads();

    int bh = blockIdx.x;
    int b = bh >> 7, h = bh & 127;
    int w = tid;

    const float* xp = x + (size_t)b * 64 * NPIX + h * WW + w;
    float xin[64];
#pragma unroll
    for (int ci = 0; ci < 64; ci++) xin[ci] = xp[(size_t)ci * NPIX];

    float4* out4 = (float4*)(g_x2 + ((size_t)bh * WW + w) * 64);
    float* outt = g_x2t + ((size_t)b * 64) * NPIX + h * WW + w;
    const float4* wsm4 = (const float4*)wsm;
    const float4* b4 = (const float4*)bsm;
#pragma unroll
    for (int cog = 0; cog < 16; cog++) {
        float4 acc = b4[cog];
#pragma unroll
        for (int ci = 0; ci < 64; ci++) {
            float4 wv = wsm4[ci * 16 + cog];
            acc.x += xin[ci] * wv.x;
            acc.y += xin[ci] * wv.y;
            acc.z += xin[ci] * wv.z;
            acc.w += xin[ci] * wv.w;
        }
        out4[cog] = acc;
        outt[(size_t)(cog * 4 + 0) * NPIX] = acc.x;
        outt[(size_t)(cog * 4 + 1) * NPIX] = acc.y;
        outt[(size_t)(cog * 4 + 2) * NPIX] = acc.z;
        outt[(size_t)(cog * 4 + 3) * NPIX] = acc.w;
    }
}

// ---------------------------------------------------------------------------
// K2: fused offset+mask 3x3 conv. block = 2 rows (256 px), 256 threads.
// xs smem [32ch][4 rows][132] (slot = col+1), 2 channel chunks.
// thread tile: 4 co x 8 px. weights via L1 from g_w2.
// ---------------------------------------------------------------------------
extern __shared__ float dyn_smem[];

__global__ void __launch_bounds__(256, 2) k2_offmask(const float* __restrict__ off_b,
                                                     const float* __restrict__ mod_b) {
    float* xs = dyn_smem;   // 32*4*132 = 16896 floats

    int tid = threadIdx.x;
    int bx = blockIdx.x;
    int b = bx >> 6, h0 = (bx & 63) * 2;

    int cg = tid & 7;               // co = cg*4 .. cg*4+3
    int pg = tid >> 3;              // 0..31
    int rrow = pg >> 4;             // row within block (0/1)
    int px0 = (pg & 15) * 8;

    float acc[4][8];
#pragma unroll
    for (int i = 0; i < 4; i++)
#pragma unroll
        for (int j = 0; j < 8; j++) acc[i][j] = 0.f;

    for (int ci0 = 0; ci0 < 64; ci0 += 32) {
        __syncthreads();
        // load xs[c_l][r][1+col], pads zero
        for (int i = tid; i < 32 * 4 * 32; i += 256) {   // float4 granularity
            int c_l = i >> 7;
            int rem = i & 127;
            int r = rem >> 5, q4 = rem & 31;
            int gy = h0 - 1 + r;
            float4 v = make_float4(0.f, 0.f, 0.f, 0.f);
            if ((unsigned)gy < 128u)
                v = ((const float4*)(g_x2t + (((size_t)(b * 64 + ci0 + c_l)) * 128 + gy) * 128))[q4];
            float* dst = xs + c_l * 528 + r * 132 + 1 + q4 * 4;
            dst[0] = v.x; dst[1] = v.y; dst[2] = v.z; dst[3] = v.w;
        }
        for (int i = tid; i < 32 * 4; i += 256) {
            int c_l = i >> 2, r = i & 3;
            float* row = xs + c_l * 528 + r * 132;
            row[0] = 0.f; row[129] = 0.f; row[130] = 0.f; row[131] = 0.f;
        }
        __syncthreads();

        for (int ci_l = 0; ci_l < 32; ci_l++) {
            const float* base = xs + ci_l * 528 + rrow * 132;
            int kbase = (ci0 + ci_l) * 9;
#pragma unroll
            for (int kk = 0; kk < 9; kk++) {
                int ky = kk / 3, kx = kk - ky * 3;
                float4 wv = __ldg((const float4*)(g_w2 + (kbase + kk) * 32 + cg * 4));
                const float* row = base + ky * 132 + px0 + kx;
#pragma unroll
                for (int j = 0; j < 8; j++) {
                    float xv = row[j];
                    acc[0][j] += wv.x * xv;
                    acc[1][j] += wv.y * xv;
                    acc[2][j] += wv.z * xv;
                    acc[3][j] += wv.w * xv;
                }
            }
        }
    }

    size_t pixbase = ((size_t)(b * 128 + h0 + rrow)) * 128 + px0;
#pragma unroll
    for (int ii = 0; ii < 4; ii++) {
        int co = cg * 4 + ii;
        if (co >= 27) continue;
        float bias = (co < 18) ? off_b[co] : mod_b[co - 18];
        bool is_mask = (co >= 18);
#pragma unroll
        for (int j = 0; j < 8; j++) {
            float v = acc[ii][j] + bias;
            if (is_mask) v = 2.0f / (1.0f + expf(-v));
            g_offm[(pixbase + j) * 32 + co] = v;
        }
    }
}

// ---------------------------------------------------------------------------
// K3: deformable sampling + contraction. block = full row (128 px), 256 threads.
// Per kk: precompute corner offsets/weights (128 threads), stage weights+samples
// in smem, then 128o x 64k x 128px GEMM chunk with 8x8 per-thread tiles.
// smem: s[64][132] | wsm[64][128] | osm[128*33] | ibuf int4[128] | wbuf float4[128]
// ---------------------------------------------------------------------------
#define S_OFF    0
#define W_OFF    8448
#define OSM_OFF  16640
#define IBUF_OFF 20864
#define WBUF_OFF 21376
#define K3_FLOATS 21888

__global__ void __launch_bounds__(256, 2) k3_main(float* __restrict__ out) {
    float* s   = dyn_smem + S_OFF;
    float* wsm = dyn_smem + W_OFF;
    float* osm = dyn_smem + OSM_OFF;
    int4*  ibuf = (int4*) (dyn_smem + IBUF_OFF);
    float4* wbuf = (float4*)(dyn_smem + WBUF_OFF);

    int tid = threadIdx.x;
    int bx = blockIdx.x;
    int b = bx >> 7, h = bx & 127;
    size_t pixbase = ((size_t)bx) * 128;

    // load per-pixel offset/mask row into padded osm
    for (int i = tid; i < 4096; i += 256) {
        int px = i >> 5, j = i & 31;
        osm[px * 33 + j] = g_offm[(pixbase + px) * 32 + j];
    }

    const float* bbase = g_x2 + (size_t)b * NPIX * 64;

    int warp = tid >> 5, lane = tid & 31;
    int pxs = lane >> 3;         // 0..3
    int c8  = lane & 7;          // channel group

    int ox = tid & 15;           // o = ox*8
    int pq = tid >> 4;           // px = pq*8

    float acc[8][8];
#pragma unroll
    for (int i = 0; i < 8; i++)
#pragma unroll
        for (int j = 0; j < 8; j++) acc[i][j] = 0.f;

    for (int kk = 0; kk < 9; kk++) {
        __syncthreads();   // previous phase B done with s/wsm; osm ready on first iter

        // precompute corner offsets + weights per pixel (threads 0..127)
        if (tid < 128) {
            int px = tid;
            int ky = kk / 3, kx = kk - ky * 3;
            float dy = osm[px * 33 + 2 * kk];
            float dx = osm[px * 33 + 2 * kk + 1];
            float m  = osm[px * 33 + 18 + kk];
            float py  = (float)(h - 1 + ky) + dy;
            float pxf = (float)(px - 1 + kx) + dx;
            float y0f = floorf(py), x0f = floorf(pxf);
            float wy = py - y0f, wx = pxf - x0f;
            int y0 = (int)y0f, x0 = (int)x0f;
            int y1 = y0 + 1, x1 = x0 + 1;
            float w00 = (1.f - wy) * (1.f - wx) * m;
            float w01 = (1.f - wy) * wx * m;
            float w10 = wy * (1.f - wx) * m;
            float w11 = wy * wx * m;
            if ((unsigned)y0 >= 128u) { w00 = 0.f; w01 = 0.f; }
            if ((unsigned)y1 >= 128u) { w10 = 0.f; w11 = 0.f; }
            if ((unsigned)x0 >= 128u) { w00 = 0.f; w10 = 0.f; }
            if ((unsigned)x1 >= 128u) { w01 = 0.f; w11 = 0.f; }
            int yc0 = min(max(y0, 0), 127), yc1 = min(max(y1, 0), 127);
            int xc0 = min(max(x0, 0), 127), xc1 = min(max(x1, 0), 127);
            ibuf[px] = make_int4((yc0 * 128 + xc0) * 64, (yc0 * 128 + xc1) * 64,
                                 (yc1 * 128 + xc0) * 64, (yc1 * 128 + xc1) * 64);
            wbuf[px] = make_float4(w00, w01, w10, w11);
        }
        // stage weights for this kk: wsm[c][o]
        {
            const float4* src = (const float4*)(g_wt + kk * 64 * 128);
            float4* dst = (float4*)wsm;
            for (int i = tid; i < 2048; i += 256) dst[i] = src[i];
        }
        __syncthreads();

        // sampling: warp covers 4 px x 32 ch per iter; 8 lanes read one 128B line
        for (int it = warp; it < 64; it += 8) {
            int half = it & 1;
            int px = (it >> 1) * 4 + pxs;
            int4 off = ibuf[px];
            float4 wt = wbuf[px];
            int cidx = half * 8 + c8;   // float4 index within 64-ch pixel
            float4 a = ((const float4*)(bbase + off.x))[cidx];
            float4 bq = ((const float4*)(bbase + off.y))[cidx];
            float4 c = ((const float4*)(bbase + off.z))[cidx];
            float4 d = ((const float4*)(bbase + off.w))[cidx];
            float v0 = wt.x * a.x + wt.y * bq.x + wt.z * c.x + wt.w * d.x;
            float v1 = wt.x * a.y + wt.y * bq.y + wt.z * c.y + wt.w * d.y;
            float v2 = wt.x * a.z + wt.y * bq.z + wt.z * c.z + wt.w * d.z;
            float v3 = wt.x * a.w + wt.y * bq.w + wt.z * c.w + wt.w * d.w;
            int cb = half * 32 + c8 * 4;
            s[(cb + 0) * 132 + px] = v0;
            s[(cb + 1) * 132 + px] = v1;
            s[(cb + 2) * 132 + px] = v2;
            s[(cb + 3) * 132 + px] = v3;
        }
        __syncthreads();

        // GEMM chunk: 128o x 64k x 128px
        const float4* w4 = (const float4*)wsm;
#pragma unroll 4
        for (int k = 0; k < 64; k++) {
            float4 wa = w4[k * 32 + ox * 2];
            float4 wb = w4[k * 32 + ox * 2 + 1];
            float4 sa = *(const float4*)(s + k * 132 + pq * 8);
            float4 sb = *(const float4*)(s + k * 132 + pq * 8 + 4);
            float wr[8] = {wa.x, wa.y, wa.z, wa.w, wb.x, wb.y, wb.z, wb.w};
            float sr[8] = {sa.x, sa.y, sa.z, sa.w, sb.x, sb.y, sb.z, sb.w};
#pragma unroll
            for (int i = 0; i < 8; i++)
#pragma unroll
                for (int j = 0; j < 8; j++) acc[i][j] += wr[i] * sr[j];
        }
    }

    // epilogue
#pragma unroll
    for (int i = 0; i < 8; i++) {
        int o = ox * 8 + i;
        float* op = out + ((size_t)(b * COUT + o)) * NPIX + h * WW + pq * 8;
        *(float4*)op = make_float4(acc[i][0], acc[i][1], acc[i][2], acc[i][3]);
        *(float4*)(op + 4) = make_float4(acc[i][4], acc[i][5], acc[i][6], acc[i][7]);
    }
}

// ---------------------------------------------------------------------------
extern "C" void kernel_launch(void* const* d_in, const int* in_sizes, int n_in,
                              void* d_out, int out_size) {
    const float* x     = (const float*)d_in[0];
    const float* pre_w = (const float*)d_in[1];
    const float* pre_b = (const float*)d_in[2];
    const float* off_w = (const float*)d_in[3];
    const float* off_b = (const float*)d_in[4];
    const float* mod_w = (const float*)d_in[5];
    const float* mod_b = (const float*)d_in[6];
    const float* reg_w = (const float*)d_in[7];
    float* out = (float*)d_out;

    const int K2_SMEM = 32 * 4 * 132 * 4;            // 67584
    const int K3_SMEM = K3_FLOATS * 4;               // 87552
    cudaFuncSetAttribute(k2_offmask, cudaFuncAttributeMaxDynamicSharedMemorySize, K2_SMEM);
    cudaFuncSetAttribute(k3_main, cudaFuncAttributeMaxDynamicSharedMemorySize, K3_SMEM);

    k0_wt<<<(KTOT * COUT + 255) / 256, 256>>>(reg_w, off_w, mod_w);
    k1_pre<<<BB * HH, 128>>>(x, pre_w, pre_b);
    k2_offmask<<<BB * HH / 2, 256, K2_SMEM>>>(off_b, mod_b);
    k3_main<<<BB * HH, 256, K3_SMEM>>>(out);
}

// round 5
// speedup vs baseline: 2.9508x; 1.4710x over previous
#include <cuda_runtime.h>
#include <cuda_bf16.h>
#include <math.h>
#include <stdint.h>

#define BB    8
#define CIN   64
#define HH    128
#define WW    128
#define COUT  128
#define NPIX  (HH*WW)           // 16384
#define KTOT  (9*CIN)           // 576

// Scratch (__device__ globals; no allocation)
__device__ float g_x2 [BB*NPIX*CIN];          // NHWC: [b][h][w][c]
__device__ float g_x2t[BB*NPIX*CIN];          // NCHW: [b][c][h][w]
__device__ float g_offm[BB*NPIX*32];          // per-pixel [32]: 0..17 off, 18..26 mask
__device__ uint4 g_wfhi[9*8*4*32];            // A frags (hi): [kk][mtile8][ks4][lane32]
__device__ uint4 g_wflo[9*8*4*32];            // A frags (lo)
__device__ float g_w2[KTOT*32];               // k2 weights padded: [ci*9+kk][co(32)]

__device__ __forceinline__ uint32_t pack_bf16x2(float e0, float e1) {
    // element0 (low 16 bits) = e0, element1 (high) = e1
    uint32_t r;
    asm("cvt.rn.bf16x2.f32 %0, %1, %2;" : "=r"(r) : "f"(e1), "f"(e0));
    return r;
}
__device__ __forceinline__ float bf16_hi(float v) {
    __nv_bfloat16 hb = __float2bfloat16(v);
    return __bfloat162float(hb);
}
__device__ __forceinline__ void mma_bf16(float* d, const uint32_t* a, uint32_t b0, uint32_t b1) {
    asm volatile(
        "mma.sync.aligned.m16n8k16.row.col.f32.bf16.bf16.f32 "
        "{%0,%1,%2,%3}, {%4,%5,%6,%7}, {%8,%9}, {%0,%1,%2,%3};"
        : "+f"(d[0]), "+f"(d[1]), "+f"(d[2]), "+f"(d[3])
        : "r"(a[0]), "r"(a[1]), "r"(a[2]), "r"(a[3]), "r"(b0), "r"(b1));
}

// ---------------------------------------------------------------------------
// K0: weight prep. A fragments pre-packed in mma register layout, hi/lo split.
// ---------------------------------------------------------------------------
__global__ void k0_wt(const float* __restrict__ rw,
                      const float* __restrict__ off_w,
                      const float* __restrict__ mod_w) {
    int i = blockIdx.x * 256 + threadIdx.x;
    if (i < 9 * 8 * 4 * 32) {
        int kk   = i >> 10;          // /1024
        int rem  = i & 1023;
        int mt   = rem >> 7;         // 0..7
        int rem2 = rem & 127;
        int ks   = rem2 >> 5;        // 0..3
        int lane = rem2 & 31;
        int g = lane >> 2, t = lane & 3;
        int o0 = mt * 16 + g, o1 = o0 + 8;
        int c0 = ks * 16 + 2 * t, c1 = c0 + 8;

        float w00a = rw[(o0 * 64 + c0) * 9 + kk];
        float w00b = rw[(o0 * 64 + c0 + 1) * 9 + kk];
        float w10a = rw[(o1 * 64 + c0) * 9 + kk];
        float w10b = rw[(o1 * 64 + c0 + 1) * 9 + kk];
        float w01a = rw[(o0 * 64 + c1) * 9 + kk];
        float w01b = rw[(o0 * 64 + c1 + 1) * 9 + kk];
        float w11a = rw[(o1 * 64 + c1) * 9 + kk];
        float w11b = rw[(o1 * 64 + c1 + 1) * 9 + kk];

        float h00a = bf16_hi(w00a), h00b = bf16_hi(w00b);
        float h10a = bf16_hi(w10a), h10b = bf16_hi(w10b);
        float h01a = bf16_hi(w01a), h01b = bf16_hi(w01b);
        float h11a = bf16_hi(w11a), h11b = bf16_hi(w11b);

        uint4 hi, lo;
        hi.x = pack_bf16x2(h00a, h00b);
        hi.y = pack_bf16x2(h10a, h10b);
        hi.z = pack_bf16x2(h01a, h01b);
        hi.w = pack_bf16x2(h11a, h11b);
        lo.x = pack_bf16x2(w00a - h00a, w00b - h00b);
        lo.y = pack_bf16x2(w10a - h10a, w10b - h10b);
        lo.z = pack_bf16x2(w01a - h01a, w01b - h01b);
        lo.w = pack_bf16x2(w11a - h11a, w11b - h11b);
        g_wfhi[i] = hi;
        g_wflo[i] = lo;
    }
    if (i < KTOT * 32) {
        int co = i & 31, k = i >> 5;
        float v = 0.f;
        if (co < 18)      v = off_w[co * 576 + k];
        else if (co < 27) v = mod_w[(co - 18) * 576 + k];
        g_w2[i] = v;
    }
}

// ---------------------------------------------------------------------------
// K1: 1x1 pre-conv, NCHW in -> NHWC (g_x2) + NCHW (g_x2t)
// ---------------------------------------------------------------------------
__global__ void __launch_bounds__(128) k1_pre(const float* __restrict__ x,
                                              const float* __restrict__ pre_w,
                                              const float* __restrict__ pre_b) {
    __shared__ float wsm[64 * 64];
    __shared__ float bsm[64];
    int tid = threadIdx.x;
    for (int i = tid; i < 4096; i += 128) {
        int co = i & 63, ci = i >> 6;
        wsm[ci * 64 + co] = pre_w[co * 64 + ci];
    }
    if (tid < 64) bsm[tid] = pre_b[tid];
    __syncthreads();

    int bh = blockIdx.x;
    int b = bh >> 7, h = bh & 127;
    int w = tid;

    const float* xp = x + (size_t)b * 64 * NPIX + h * WW + w;
    float xin[64];
#pragma unroll
    for (int ci = 0; ci < 64; ci++) xin[ci] = xp[(size_t)ci * NPIX];

    float4* out4 = (float4*)(g_x2 + ((size_t)bh * WW + w) * 64);
    float* outt = g_x2t + ((size_t)b * 64) * NPIX + h * WW + w;
    const float4* wsm4 = (const float4*)wsm;
    const float4* b4 = (const float4*)bsm;
#pragma unroll
    for (int cog = 0; cog < 16; cog++) {
        float4 acc = b4[cog];
#pragma unroll
        for (int ci = 0; ci < 64; ci++) {
            float4 wv = wsm4[ci * 16 + cog];
            acc.x += xin[ci] * wv.x;
            acc.y += xin[ci] * wv.y;
            acc.z += xin[ci] * wv.z;
            acc.w += xin[ci] * wv.w;
        }
        out4[cog] = acc;
        outt[(size_t)(cog * 4 + 0) * NPIX] = acc.x;
        outt[(size_t)(cog * 4 + 1) * NPIX] = acc.y;
        outt[(size_t)(cog * 4 + 2) * NPIX] = acc.z;
        outt[(size_t)(cog * 4 + 3) * NPIX] = acc.w;
    }
}

// ---------------------------------------------------------------------------
// K2: fused offset+mask 3x3 conv
// ---------------------------------------------------------------------------
extern __shared__ float dyn_smem[];

__global__ void __launch_bounds__(256, 2) k2_offmask(const float* __restrict__ off_b,
                                                     const float* __restrict__ mod_b) {
    float* xs = dyn_smem;

    int tid = threadIdx.x;
    int bx = blockIdx.x;
    int b = bx >> 6, h0 = (bx & 63) * 2;

    int cg = tid & 7;
    int pg = tid >> 3;
    int rrow = pg >> 4;
    int px0 = (pg & 15) * 8;

    float acc[4][8];
#pragma unroll
    for (int i = 0; i < 4; i++)
#pragma unroll
        for (int j = 0; j < 8; j++) acc[i][j] = 0.f;

    for (int ci0 = 0; ci0 < 64; ci0 += 32) {
        __syncthreads();
        for (int i = tid; i < 32 * 4 * 32; i += 256) {
            int c_l = i >> 7;
            int rem = i & 127;
            int r = rem >> 5, q4 = rem & 31;
            int gy = h0 - 1 + r;
            float4 v = make_float4(0.f, 0.f, 0.f, 0.f);
            if ((unsigned)gy < 128u)
                v = ((const float4*)(g_x2t + (((size_t)(b * 64 + ci0 + c_l)) * 128 + gy) * 128))[q4];
            float* dst = xs + c_l * 528 + r * 132 + 1 + q4 * 4;
            dst[0] = v.x; dst[1] = v.y; dst[2] = v.z; dst[3] = v.w;
        }
        for (int i = tid; i < 32 * 4; i += 256) {
            int c_l = i >> 2, r = i & 3;
            float* row = xs + c_l * 528 + r * 132;
            row[0] = 0.f; row[129] = 0.f; row[130] = 0.f; row[131] = 0.f;
        }
        __syncthreads();

        for (int ci_l = 0; ci_l < 32; ci_l++) {
            const float* base = xs + ci_l * 528 + rrow * 132;
            int kbase = (ci0 + ci_l) * 9;
#pragma unroll
            for (int kk = 0; kk < 9; kk++) {
                int ky = kk / 3, kx = kk - ky * 3;
                float4 wv = __ldg((const float4*)(g_w2 + (kbase + kk) * 32 + cg * 4));
                const float* row = base + ky * 132 + px0 + kx;
#pragma unroll
                for (int j = 0; j < 8; j++) {
                    float xv = row[j];
                    acc[0][j] += wv.x * xv;
                    acc[1][j] += wv.y * xv;
                    acc[2][j] += wv.z * xv;
                    acc[3][j] += wv.w * xv;
                }
            }
        }
    }

    size_t pixbase = ((size_t)(b * 128 + h0 + rrow)) * 128 + px0;
#pragma unroll
    for (int ii = 0; ii < 4; ii++) {
        int co = cg * 4 + ii;
        if (co >= 27) continue;
        float bias = (co < 18) ? off_b[co] : mod_b[co - 18];
        bool is_mask = (co >= 18);
#pragma unroll
        for (int j = 0; j < 8; j++) {
            float v = acc[ii][j] + bias;
            if (is_mask) v = 2.0f / (1.0f + expf(-v));
            g_offm[(pixbase + j) * 32 + co] = v;
        }
    }
}

// ---------------------------------------------------------------------------
// K3: deformable sampling + HMMA (mma.sync bf16 hi/lo 3-pass) contraction.
// Block = one row (128 px), 512 threads / 16 warps.
// Warp tile: 32 o x 32 px (2 m-tiles x 4 n-tiles of m16n8k16).
// smem (bytes):
//   S_HI   0       128*72 bf16 = 18432      samples hi  [px][72]
//   S_LO   18432   18432                    samples lo
//   OSM    36864   128*33*4 = 16896
//   IBUF   53760   9*128*16 = 18432         corner offsets (int4)
//   WBUF   72192   18432                    corner weights (float4)
// total 90624 B
// ---------------------------------------------------------------------------
#define S_HI_OFF  0
#define S_LO_OFF  18432
#define OSM_OFF   36864
#define IBUF_OFF  53760
#define WBUF_OFF  72192
#define K3_SMEM_BYTES 90624
#define S_STRIDE  144   // bytes per px row (72 bf16)

__global__ void __launch_bounds__(512, 1) k3_main(float* __restrict__ out) {
    char* smp = (char*)dyn_smem;

    int tid = threadIdx.x;
    int warp = tid >> 5, lane = tid & 31;
    int g = lane >> 2, t = lane & 3;
    int bx = blockIdx.x;
    int b = bx >> 7, h = bx & 127;
    size_t pixbase = ((size_t)bx) * 128;

    float* osm = (float*)(smp + OSM_OFF);
    int4* ibuf = (int4*)(smp + IBUF_OFF);
    float4* wbuf = (float4*)(smp + WBUF_OFF);
    char* s_hi = smp + S_HI_OFF;
    char* s_lo = smp + S_LO_OFF;

    // offsets/masks for the row
    for (int i = tid; i < 4096; i += 512) {
        int px = i >> 5, j = i & 31;
        osm[px * 33 + j] = g_offm[(pixbase + px) * 32 + j];
    }
    __syncthreads();

    // precompute all corner indices/weights: 9 kk x 128 px
    for (int i = tid; i < 9 * 128; i += 512) {
        int kk = i >> 7, px = i & 127;
        int ky = kk / 3, kx = kk - ky * 3;
        float dy = osm[px * 33 + 2 * kk];
        float dx = osm[px * 33 + 2 * kk + 1];
        float m  = osm[px * 33 + 18 + kk];
        float py  = (float)(h - 1 + ky) + dy;
        float pxf = (float)(px - 1 + kx) + dx;
        float y0f = floorf(py), x0f = floorf(pxf);
        float wy = py - y0f, wx = pxf - x0f;
        int y0 = (int)y0f, x0 = (int)x0f;
        int y1 = y0 + 1, x1 = x0 + 1;
        float w00 = (1.f - wy) * (1.f - wx) * m;
        float w01 = (1.f - wy) * wx * m;
        float w10 = wy * (1.f - wx) * m;
        float w11 = wy * wx * m;
        if ((unsigned)y0 >= 128u) { w00 = 0.f; w01 = 0.f; }
        if ((unsigned)y1 >= 128u) { w10 = 0.f; w11 = 0.f; }
        if ((unsigned)x0 >= 128u) { w00 = 0.f; w10 = 0.f; }
        if ((unsigned)x1 >= 128u) { w01 = 0.f; w11 = 0.f; }
        int yc0 = min(max(y0, 0), 127), yc1 = min(max(y1, 0), 127);
        int xc0 = min(max(x0, 0), 127), xc1 = min(max(x1, 0), 127);
        ibuf[i] = make_int4((yc0 * 128 + xc0) * 64, (yc0 * 128 + xc1) * 64,
                            (yc1 * 128 + xc0) * 64, (yc1 * 128 + xc1) * 64);
        wbuf[i] = make_float4(w00, w01, w10, w11);
    }

    const float* bbase = g_x2 + (size_t)b * NPIX * 64;
    int pxs = lane >> 3;     // 0..3
    int c8  = lane & 7;      // 0..7

    int warp_m = warp >> 2;          // 0..3 -> o base = warp_m*32
    int warp_n = warp & 3;           // 0..3 -> px base = warp_n*32

    float acc[2][4][4];
#pragma unroll
    for (int mt = 0; mt < 2; mt++)
#pragma unroll
        for (int nt = 0; nt < 4; nt++)
#pragma unroll
            for (int j = 0; j < 4; j++) acc[mt][nt][j] = 0.f;

    for (int kk = 0; kk < 9; kk++) {
        __syncthreads();   // prev mma done reading s (and ibuf ready on first iter)

        // ---- sampling: bilinear gather -> bf16 hi/lo smem ----
        const int4* ib = ibuf + kk * 128;
        const float4* wb = wbuf + kk * 128;
        for (int it = warp; it < 64; it += 16) {
            int half = it & 1;
            int px = (it >> 1) * 4 + pxs;
            int4 off = ib[px];
            float4 wt = wb[px];
            int c4 = half * 8 + c8;    // float4 channel group (0..15)
            float4 a = ((const float4*)(bbase + off.x))[c4];
            float4 bq = ((const float4*)(bbase + off.y))[c4];
            float4 c = ((const float4*)(bbase + off.z))[c4];
            float4 d = ((const float4*)(bbase + off.w))[c4];
            float v0 = wt.x * a.x + wt.y * bq.x + wt.z * c.x + wt.w * d.x;
            float v1 = wt.x * a.y + wt.y * bq.y + wt.z * c.y + wt.w * d.y;
            float v2 = wt.x * a.z + wt.y * bq.z + wt.z * c.z + wt.w * d.z;
            float v3 = wt.x * a.w + wt.y * bq.w + wt.z * c.w + wt.w * d.w;

            float h0 = bf16_hi(v0), h1 = bf16_hi(v1);
            float h2 = bf16_hi(v2), h3 = bf16_hi(v3);
            uint32_t hi01 = pack_bf16x2(h0, h1);
            uint32_t hi23 = pack_bf16x2(h2, h3);
            uint32_t lo01 = pack_bf16x2(v0 - h0, v1 - h1);
            uint32_t lo23 = pack_bf16x2(v2 - h2, v3 - h3);

            uint32_t byte = (uint32_t)(px * S_STRIDE + c4 * 8);
            *(uint2*)(s_hi + byte) = make_uint2(hi01, hi23);
            *(uint2*)(s_lo + byte) = make_uint2(lo01, lo23);
        }
        __syncthreads();

        // ---- HMMA: 3-pass hi/lo ----
        const uint4* wf_hi = g_wfhi + (kk * 8) * 4 * 32;
        const uint4* wf_lo = g_wflo + (kk * 8) * 4 * 32;
#pragma unroll
        for (int ks = 0; ks < 4; ks++) {
            // A hi frags for 2 m-tiles
            uint4 ah0 = __ldg(&wf_hi[((warp_m * 2 + 0) * 4 + ks) * 32 + lane]);
            uint4 ah1 = __ldg(&wf_hi[((warp_m * 2 + 1) * 4 + ks) * 32 + lane]);
            // B hi/lo frags for 4 n-tiles
            uint32_t bh0[4], bh1[4], bl0[4], bl1[4];
#pragma unroll
            for (int nt = 0; nt < 4; nt++) {
                int npx = warp_n * 32 + nt * 8 + g;
                uint32_t base = (uint32_t)(npx * S_STRIDE + ks * 32 + t * 4);
                bh0[nt] = *(const uint32_t*)(s_hi + base);
                bh1[nt] = *(const uint32_t*)(s_hi + base + 16);
                bl0[nt] = *(const uint32_t*)(s_lo + base);
                bl1[nt] = *(const uint32_t*)(s_lo + base + 16);
            }
#pragma unroll
            for (int nt = 0; nt < 4; nt++) {
                mma_bf16(acc[0][nt], (const uint32_t*)&ah0, bh0[nt], bh1[nt]);
                mma_bf16(acc[1][nt], (const uint32_t*)&ah1, bh0[nt], bh1[nt]);
                mma_bf16(acc[0][nt], (const uint32_t*)&ah0, bl0[nt], bl1[nt]);
                mma_bf16(acc[1][nt], (const uint32_t*)&ah1, bl0[nt], bl1[nt]);
            }
            // A lo frags (reuse regs)
            uint4 al0 = __ldg(&wf_lo[((warp_m * 2 + 0) * 4 + ks) * 32 + lane]);
            uint4 al1 = __ldg(&wf_lo[((warp_m * 2 + 1) * 4 + ks) * 32 + lane]);
#pragma unroll
            for (int nt = 0; nt < 4; nt++) {
                mma_bf16(acc[0][nt], (const uint32_t*)&al0, bh0[nt], bh1[nt]);
                mma_bf16(acc[1][nt], (const uint32_t*)&al1, bh0[nt], bh1[nt]);
            }
        }
    }

    // ---- epilogue: direct STG from C fragments ----
    float* ob = out + ((size_t)b * COUT) * NPIX + h * WW;
#pragma unroll
    for (int mt = 0; mt < 2; mt++) {
        int o = warp_m * 32 + mt * 16 + g;
#pragma unroll
        for (int nt = 0; nt < 4; nt++) {
            int px = warp_n * 32 + nt * 8 + 2 * t;
            float* p0 = ob + (size_t)o * NPIX + px;
            *(float2*)p0 = make_float2(acc[mt][nt][0], acc[mt][nt][1]);
            float* p1 = p0 + 8 * (size_t)NPIX;
            *(float2*)p1 = make_float2(acc[mt][nt][2], acc[mt][nt][3]);
        }
    }
}

// ---------------------------------------------------------------------------
extern "C" void kernel_launch(void* const* d_in, const int* in_sizes, int n_in,
                              void* d_out, int out_size) {
    const float* x     = (const float*)d_in[0];
    const float* pre_w = (const float*)d_in[1];
    const float* pre_b = (const float*)d_in[2];
    const float* off_w = (const float*)d_in[3];
    const float* off_b = (const float*)d_in[4];
    const float* mod_w = (const float*)d_in[5];
    const float* mod_b = (const float*)d_in[6];
    const float* reg_w = (const float*)d_in[7];
    float* out = (float*)d_out;

    const int K2_SMEM = 32 * 4 * 132 * 4;
    cudaFuncSetAttribute(k2_offmask, cudaFuncAttributeMaxDynamicSharedMemorySize, K2_SMEM);
    cudaFuncSetAttribute(k3_main, cudaFuncAttributeMaxDynamicSharedMemorySize, K3_SMEM_BYTES);

    k0_wt<<<(KTOT * 32 + 255) / 256, 256>>>(reg_w, off_w, mod_w);
    k1_pre<<<BB * HH, 128>>>(x, pre_w, pre_b);
    k2_offmask<<<BB * HH / 2, 256, K2_SMEM>>>(off_b, mod_b);
    k3_main<<<BB * HH, 512, K3_SMEM_BYTES>>>(out);
}

// round 6
// speedup vs baseline: 3.0727x; 1.0413x over previous
#include <cuda_runtime.h>
#include <cuda_bf16.h>
#include <math.h>
#include <stdint.h>

#define BB    8
#define CIN   64
#define HH    128
#define WW    128
#define COUT  128
#define NPIX  (HH*WW)           // 16384
#define KTOT  (9*CIN)           // 576

// Scratch (__device__ globals; no allocation)
__device__ float g_x2 [BB*NPIX*CIN];          // NHWC: [b][h][w][c]
__device__ float g_x2t[BB*NPIX*CIN];          // NCHW: [b][c][h][w]
__device__ float g_offm[BB*NPIX*32];          // per-pixel [32]: 0..17 off, 18..26 mask
__device__ uint4 g_wfhi[9*8*4*32];            // A frags (hi): [kk][mtile8][ks4][lane32]
__device__ uint4 g_wflo[9*8*4*32];            // A frags (lo)
__device__ float g_w2[KTOT*32];               // k2 weights padded: [ci*9+kk][co(32)]

__device__ __forceinline__ uint32_t pack_bf16x2(float e0, float e1) {
    uint32_t r;
    asm("cvt.rn.bf16x2.f32 %0, %1, %2;" : "=r"(r) : "f"(e1), "f"(e0));
    return r;
}
__device__ __forceinline__ float bf16_hi(float v) {
    __nv_bfloat16 hb = __float2bfloat16(v);
    return __bfloat162float(hb);
}
__device__ __forceinline__ void mma_bf16(float* d, const uint32_t* a, uint32_t b0, uint32_t b1) {
    asm volatile(
        "mma.sync.aligned.m16n8k16.row.col.f32.bf16.bf16.f32 "
        "{%0,%1,%2,%3}, {%4,%5,%6,%7}, {%8,%9}, {%0,%1,%2,%3};"
        : "+f"(d[0]), "+f"(d[1]), "+f"(d[2]), "+f"(d[3])
        : "r"(a[0]), "r"(a[1]), "r"(a[2]), "r"(a[3]), "r"(b0), "r"(b1));
}

// ---------------------------------------------------------------------------
// K0: weight prep. A fragments pre-packed in mma register layout, hi/lo split.
// ---------------------------------------------------------------------------
__global__ void k0_wt(const float* __restrict__ rw,
                      const float* __restrict__ off_w,
                      const float* __restrict__ mod_w) {
    int i = blockIdx.x * 256 + threadIdx.x;
    if (i < 9 * 8 * 4 * 32) {
        int kk   = i >> 10;
        int rem  = i & 1023;
        int mt   = rem >> 7;
        int rem2 = rem & 127;
        int ks   = rem2 >> 5;
        int lane = rem2 & 31;
        int g = lane >> 2, t = lane & 3;
        int o0 = mt * 16 + g, o1 = o0 + 8;
        int c0 = ks * 16 + 2 * t, c1 = c0 + 8;

        float w00a = rw[(o0 * 64 + c0) * 9 + kk];
        float w00b = rw[(o0 * 64 + c0 + 1) * 9 + kk];
        float w10a = rw[(o1 * 64 + c0) * 9 + kk];
        float w10b = rw[(o1 * 64 + c0 + 1) * 9 + kk];
        float w01a = rw[(o0 * 64 + c1) * 9 + kk];
        float w01b = rw[(o0 * 64 + c1 + 1) * 9 + kk];
        float w11a = rw[(o1 * 64 + c1) * 9 + kk];
        float w11b = rw[(o1 * 64 + c1 + 1) * 9 + kk];

        float h00a = bf16_hi(w00a), h00b = bf16_hi(w00b);
        float h10a = bf16_hi(w10a), h10b = bf16_hi(w10b);
        float h01a = bf16_hi(w01a), h01b = bf16_hi(w01b);
        float h11a = bf16_hi(w11a), h11b = bf16_hi(w11b);

        uint4 hi, lo;
        hi.x = pack_bf16x2(h00a, h00b);
        hi.y = pack_bf16x2(h10a, h10b);
        hi.z = pack_bf16x2(h01a, h01b);
        hi.w = pack_bf16x2(h11a, h11b);
        lo.x = pack_bf16x2(w00a - h00a, w00b - h00b);
        lo.y = pack_bf16x2(w10a - h10a, w10b - h10b);
        lo.z = pack_bf16x2(w01a - h01a, w01b - h01b);
        lo.w = pack_bf16x2(w11a - h11a, w11b - h11b);
        g_wfhi[i] = hi;
        g_wflo[i] = lo;
    }
    if (i < KTOT * 32) {
        int co = i & 31, k = i >> 5;
        float v = 0.f;
        if (co < 18)      v = off_w[co * 576 + k];
        else if (co < 27) v = mod_w[(co - 18) * 576 + k];
        g_w2[i] = v;
    }
}

// ---------------------------------------------------------------------------
// K1: 1x1 pre-conv, NCHW in -> NHWC (g_x2) + NCHW (g_x2t)
// ---------------------------------------------------------------------------
__global__ void __launch_bounds__(128) k1_pre(const float* __restrict__ x,
                                              const float* __restrict__ pre_w,
                                              const float* __restrict__ pre_b) {
    __shared__ float wsm[64 * 64];
    __shared__ float bsm[64];
    int tid = threadIdx.x;
    for (int i = tid; i < 4096; i += 128) {
        int co = i & 63, ci = i >> 6;
        wsm[ci * 64 + co] = pre_w[co * 64 + ci];
    }
    if (tid < 64) bsm[tid] = pre_b[tid];
    __syncthreads();

    int bh = blockIdx.x;
    int b = bh >> 7, h = bh & 127;
    int w = tid;

    const float* xp = x + (size_t)b * 64 * NPIX + h * WW + w;
    float xin[64];
#pragma unroll
    for (int ci = 0; ci < 64; ci++) xin[ci] = xp[(size_t)ci * NPIX];

    float4* out4 = (float4*)(g_x2 + ((size_t)bh * WW + w) * 64);
    float* outt = g_x2t + ((size_t)b * 64) * NPIX + h * WW + w;
    const float4* wsm4 = (const float4*)wsm;
    const float4* b4 = (const float4*)bsm;
#pragma unroll
    for (int cog = 0; cog < 16; cog++) {
        float4 acc = b4[cog];
#pragma unroll
        for (int ci = 0; ci < 64; ci++) {
            float4 wv = wsm4[ci * 16 + cog];
            acc.x += xin[ci] * wv.x;
            acc.y += xin[ci] * wv.y;
            acc.z += xin[ci] * wv.z;
            acc.w += xin[ci] * wv.w;
        }
        out4[cog] = acc;
        outt[(size_t)(cog * 4 + 0) * NPIX] = acc.x;
        outt[(size_t)(cog * 4 + 1) * NPIX] = acc.y;
        outt[(size_t)(cog * 4 + 2) * NPIX] = acc.z;
        outt[(size_t)(cog * 4 + 3) * NPIX] = acc.w;
    }
}

// ---------------------------------------------------------------------------
// K2: fused offset+mask 3x3 conv
// ---------------------------------------------------------------------------
extern __shared__ float dyn_smem[];

__global__ void __launch_bounds__(256, 2) k2_offmask(const float* __restrict__ off_b,
                                                     const float* __restrict__ mod_b) {
    float* xs = dyn_smem;

    int tid = threadIdx.x;
    int bx = blockIdx.x;
    int b = bx >> 6, h0 = (bx & 63) * 2;

    int cg = tid & 7;
    int pg = tid >> 3;
    int rrow = pg >> 4;
    int px0 = (pg & 15) * 8;

    float acc[4][8];
#pragma unroll
    for (int i = 0; i < 4; i++)
#pragma unroll
        for (int j = 0; j < 8; j++) acc[i][j] = 0.f;

    for (int ci0 = 0; ci0 < 64; ci0 += 32) {
        __syncthreads();
        for (int i = tid; i < 32 * 4 * 32; i += 256) {
            int c_l = i >> 7;
            int rem = i & 127;
            int r = rem >> 5, q4 = rem & 31;
            int gy = h0 - 1 + r;
            float4 v = make_float4(0.f, 0.f, 0.f, 0.f);
            if ((unsigned)gy < 128u)
                v = ((const float4*)(g_x2t + (((size_t)(b * 64 + ci0 + c_l)) * 128 + gy) * 128))[q4];
            float* dst = xs + c_l * 528 + r * 132 + 1 + q4 * 4;
            dst[0] = v.x; dst[1] = v.y; dst[2] = v.z; dst[3] = v.w;
        }
        for (int i = tid; i < 32 * 4; i += 256) {
            int c_l = i >> 2, r = i & 3;
            float* row = xs + c_l * 528 + r * 132;
            row[0] = 0.f; row[129] = 0.f; row[130] = 0.f; row[131] = 0.f;
        }
        __syncthreads();

        for (int ci_l = 0; ci_l < 32; ci_l++) {
            const float* base = xs + ci_l * 528 + rrow * 132;
            int kbase = (ci0 + ci_l) * 9;
#pragma unroll
            for (int kk = 0; kk < 9; kk++) {
                int ky = kk / 3, kx = kk - ky * 3;
                float4 wv = __ldg((const float4*)(g_w2 + (kbase + kk) * 32 + cg * 4));
                const float* row = base + ky * 132 + px0 + kx;
#pragma unroll
                for (int j = 0; j < 8; j++) {
                    float xv = row[j];
                    acc[0][j] += wv.x * xv;
                    acc[1][j] += wv.y * xv;
                    acc[2][j] += wv.z * xv;
                    acc[3][j] += wv.w * xv;
                }
            }
        }
    }

    size_t pixbase = ((size_t)(b * 128 + h0 + rrow)) * 128 + px0;
#pragma unroll
    for (int ii = 0; ii < 4; ii++) {
        int co = cg * 4 + ii;
        if (co >= 27) continue;
        float bias = (co < 18) ? off_b[co] : mod_b[co - 18];
        bool is_mask = (co >= 18);
#pragma unroll
        for (int j = 0; j < 8; j++) {
            float v = acc[ii][j] + bias;
            if (is_mask) v = 2.0f / (1.0f + expf(-v));
            g_offm[(pixbase + j) * 32 + co] = v;
        }
    }
}

// ---------------------------------------------------------------------------
// K3: deformable sampling + HMMA (bf16 hi/lo 3-pass).
// Block = HALF row (64 px), 256 threads / 8 warps, 2 CTAs per SM
// (256 thr x 128 regs x 2 = full RF) -> inter-CTA phase overlap.
// Warp tile: 32 o x 32 px (2 m-tiles x 4 n-tiles of m16n8k16).
// smem (bytes):
//   S_HI   0       64*144 = 9216    samples hi [px][72 bf16]
//   S_LO   9216    9216             samples lo
//   OSM    18432   64*33*4 = 8448
//   IBUF   26880   9*64*16 = 9216   corner offsets (int4)
//   WBUF   36096   9216             corner weights (float4)
// total 45312 B  (x2 CTAs = 90624 < 227K)
// ---------------------------------------------------------------------------
#define S_HI_OFF  0
#define S_LO_OFF  9216
#define OSM_OFF   18432
#define IBUF_OFF  26880
#define WBUF_OFF  36096
#define K3_SMEM_BYTES 45312
#define S_STRIDE  144   // bytes per px row (72 bf16)

__global__ void __launch_bounds__(256, 2) k3_main(float* __restrict__ out) {
    char* smp = (char*)dyn_smem;

    int tid = threadIdx.x;
    int warp = tid >> 5, lane = tid & 31;
    int g = lane >> 2, t = lane & 3;
    int bx = blockIdx.x;
    int b = bx >> 8;                 // 2048 blocks: [b][h][seg]
    int h = (bx >> 1) & 127;
    int seg = bx & 1;
    int w0 = seg * 64;
    size_t pixbase = (((size_t)(b * 128 + h)) * 128 + w0);

    float* osm = (float*)(smp + OSM_OFF);
    int4* ibuf = (int4*)(smp + IBUF_OFF);
    float4* wbuf = (float4*)(smp + WBUF_OFF);
    char* s_hi = smp + S_HI_OFF;
    char* s_lo = smp + S_LO_OFF;

    // offsets/masks for the 64 px
    for (int i = tid; i < 2048; i += 256) {
        int px = i >> 5, j = i & 31;
        osm[px * 33 + j] = g_offm[(pixbase + px) * 32 + j];
    }
    __syncthreads();

    // precompute corner indices/weights: 9 kk x 64 px
    for (int i = tid; i < 9 * 64; i += 256) {
        int kk = i >> 6, px = i & 63;
        int ky = kk / 3, kx = kk - ky * 3;
        float dy = osm[px * 33 + 2 * kk];
        float dx = osm[px * 33 + 2 * kk + 1];
        float m  = osm[px * 33 + 18 + kk];
        float py  = (float)(h - 1 + ky) + dy;
        float pxf = (float)(w0 + px - 1 + kx) + dx;
        float y0f = floorf(py), x0f = floorf(pxf);
        float wy = py - y0f, wx = pxf - x0f;
        int y0 = (int)y0f, x0 = (int)x0f;
        int y1 = y0 + 1, x1 = x0 + 1;
        float w00 = (1.f - wy) * (1.f - wx) * m;
        float w01 = (1.f - wy) * wx * m;
        float w10 = wy * (1.f - wx) * m;
        float w11 = wy * wx * m;
        if ((unsigned)y0 >= 128u) { w00 = 0.f; w01 = 0.f; }
        if ((unsigned)y1 >= 128u) { w10 = 0.f; w11 = 0.f; }
        if ((unsigned)x0 >= 128u) { w00 = 0.f; w10 = 0.f; }
        if ((unsigned)x1 >= 128u) { w01 = 0.f; w11 = 0.f; }
        int yc0 = min(max(y0, 0), 127), yc1 = min(max(y1, 0), 127);
        int xc0 = min(max(x0, 0), 127), xc1 = min(max(x1, 0), 127);
        ibuf[i] = make_int4((yc0 * 128 + xc0) * 64, (yc0 * 128 + xc1) * 64,
                            (yc1 * 128 + xc0) * 64, (yc1 * 128 + xc1) * 64);
        wbuf[i] = make_float4(w00, w01, w10, w11);
    }

    const float* bbase = g_x2 + (size_t)b * NPIX * 64;
    int pxs = lane >> 3;     // 0..3
    int c8  = lane & 7;      // 0..7

    int warp_m = warp >> 1;          // 0..3 -> o base = warp_m*32
    int warp_n = warp & 1;           // 0..1 -> px base = warp_n*32

    float acc[2][4][4];
#pragma unroll
    for (int mt = 0; mt < 2; mt++)
#pragma unroll
        for (int nt = 0; nt < 4; nt++)
#pragma unroll
            for (int j = 0; j < 4; j++) acc[mt][nt][j] = 0.f;

    for (int kk = 0; kk < 9; kk++) {
        __syncthreads();   // prev mma done reading s (and ibuf ready on first iter)

        // ---- sampling: bilinear gather -> bf16 hi/lo smem ----
        const int4* ib = ibuf + kk * 64;
        const float4* wb = wbuf + kk * 64;
        for (int it = warp; it < 32; it += 8) {
            int half = it & 1;
            int px = (it >> 1) * 4 + pxs;
            int4 off = ib[px];
            float4 wt = wb[px];
            int c4 = half * 8 + c8;    // float4 channel group (0..15)
            float4 a = ((const float4*)(bbase + off.x))[c4];
            float4 bq = ((const float4*)(bbase + off.y))[c4];
            float4 c = ((const float4*)(bbase + off.z))[c4];
            float4 d = ((const float4*)(bbase + off.w))[c4];
            float v0 = wt.x * a.x + wt.y * bq.x + wt.z * c.x + wt.w * d.x;
            float v1 = wt.x * a.y + wt.y * bq.y + wt.z * c.y + wt.w * d.y;
            float v2 = wt.x * a.z + wt.y * bq.z + wt.z * c.z + wt.w * d.z;
            float v3 = wt.x * a.w + wt.y * bq.w + wt.z * c.w + wt.w * d.w;

            float h0 = bf16_hi(v0), h1 = bf16_hi(v1);
            float h2 = bf16_hi(v2), h3 = bf16_hi(v3);
            uint32_t hi01 = pack_bf16x2(h0, h1);
            uint32_t hi23 = pack_bf16x2(h2, h3);
            uint32_t lo01 = pack_bf16x2(v0 - h0, v1 - h1);
            uint32_t lo23 = pack_bf16x2(v2 - h2, v3 - h3);

            uint32_t byte = (uint32_t)(px * S_STRIDE + c4 * 8);
            *(uint2*)(s_hi + byte) = make_uint2(hi01, hi23);
            *(uint2*)(s_lo + byte) = make_uint2(lo01, lo23);
        }
        __syncthreads();

        // ---- HMMA: 3-pass hi/lo ----
        const uint4* wf_hi = g_wfhi + (kk * 8) * 4 * 32;
        const uint4* wf_lo = g_wflo + (kk * 8) * 4 * 32;
#pragma unroll
        for (int ks = 0; ks < 4; ks++) {
            uint4 ah0 = __ldg(&wf_hi[((warp_m * 2 + 0) * 4 + ks) * 32 + lane]);
            uint4 ah1 = __ldg(&wf_hi[((warp_m * 2 + 1) * 4 + ks) * 32 + lane]);
            uint32_t bh0[4], bh1[4], bl0[4], bl1[4];
#pragma unroll
            for (int nt = 0; nt < 4; nt++) {
                int npx = warp_n * 32 + nt * 8 + g;
                uint32_t base = (uint32_t)(npx * S_STRIDE + ks * 32 + t * 4);
                bh0[nt] = *(const uint32_t*)(s_hi + base);
                bh1[nt] = *(const uint32_t*)(s_hi + base + 16);
                bl0[nt] = *(const uint32_t*)(s_lo + base);
                bl1[nt] = *(const uint32_t*)(s_lo + base + 16);
            }
#pragma unroll
            for (int nt = 0; nt < 4; nt++) {
                mma_bf16(acc[0][nt], (const uint32_t*)&ah0, bh0[nt], bh1[nt]);
                mma_bf16(acc[1][nt], (const uint32_t*)&ah1, bh0[nt], bh1[nt]);
                mma_bf16(acc[0][nt], (const uint32_t*)&ah0, bl0[nt], bl1[nt]);
                mma_bf16(acc[1][nt], (const uint32_t*)&ah1, bl0[nt], bl1[nt]);
            }
            uint4 al0 = __ldg(&wf_lo[((warp_m * 2 + 0) * 4 + ks) * 32 + lane]);
            uint4 al1 = __ldg(&wf_lo[((warp_m * 2 + 1) * 4 + ks) * 32 + lane]);
#pragma unroll
            for (int nt = 0; nt < 4; nt++) {
                mma_bf16(acc[0][nt], (const uint32_t*)&al0, bh0[nt], bh1[nt]);
                mma_bf16(acc[1][nt], (const uint32_t*)&al1, bh0[nt], bh1[nt]);
            }
        }
    }

    // ---- epilogue: direct STG from C fragments ----
    float* ob = out + ((size_t)b * COUT) * NPIX + h * WW + w0;
#pragma unroll
    for (int mt = 0; mt < 2; mt++) {
        int o = warp_m * 32 + mt * 16 + g;
#pragma unroll
        for (int nt = 0; nt < 4; nt++) {
            int px = warp_n * 32 + nt * 8 + 2 * t;
            float* p0 = ob + (size_t)o * NPIX + px;
            *(float2*)p0 = make_float2(acc[mt][nt][0], acc[mt][nt][1]);
            float* p1 = p0 + 8 * (size_t)NPIX;
            *(float2*)p1 = make_float2(acc[mt][nt][2], acc[mt][nt][3]);
        }
    }
}

// ---------------------------------------------------------------------------
extern "C" void kernel_launch(void* const* d_in, const int* in_sizes, int n_in,
                              void* d_out, int out_size) {
    const float* x     = (const float*)d_in[0];
    const float* pre_w = (const float*)d_in[1];
    const float* pre_b = (const float*)d_in[2];
    const float* off_w = (const float*)d_in[3];
    const float* off_b = (const float*)d_in[4];
    const float* mod_w = (const float*)d_in[5];
    const float* mod_b = (const float*)d_in[6];
    const float* reg_w = (const float*)d_in[7];
    float* out = (float*)d_out;

    const int K2_SMEM = 32 * 4 * 132 * 4;
    cudaFuncSetAttribute(k2_offmask, cudaFuncAttributeMaxDynamicSharedMemorySize, K2_SMEM);
    cudaFuncSetAttribute(k3_main, cudaFuncAttributeMaxDynamicSharedMemorySize, K3_SMEM_BYTES);

    k0_wt<<<(KTOT * 32 + 255) / 256, 256>>>(reg_w, off_w, mod_w);
    k1_pre<<<BB * HH, 128>>>(x, pre_w, pre_b);
    k2_offmask<<<BB * HH / 2, 256, K2_SMEM>>>(off_b, mod_b);
    k3_main<<<BB * HH * 2, 256, K3_SMEM_BYTES>>>(out);
}

// round 7
// speedup vs baseline: 3.6726x; 1.1952x over previous
#include <cuda_runtime.h>
#include <cuda_bf16.h>
#include <math.h>
#include <stdint.h>

#define BB    8
#define CIN   64
#define HH    128
#define WW    128
#define COUT  128
#define NPIX  (HH*WW)           // 16384
#define KTOT  (9*CIN)           // 576

// Scratch (__device__ globals; no allocation)
__device__ float g_x2 [BB*NPIX*CIN];          // NHWC fp32: [b][h][w][c]
__device__ __nv_bfloat16 g_xbhi[BB*NPIX*CIN]; // NHWC bf16 hi
__device__ __nv_bfloat16 g_xblo[BB*NPIX*CIN]; // NHWC bf16 lo
__device__ float g_offm[BB*NPIX*32];          // per-pixel [32]: 0..17 off, 18..26 mask
__device__ uint4 g_wfhi[9*8*4*32];            // k3 A frags (hi): [kk][mtile8][ks4][lane32]
__device__ uint4 g_wflo[9*8*4*32];            // k3 A frags (lo)
__device__ uint4 g_w2fhi[9*2*4*32];           // k2 A frags (hi): [kk][mtile2][ks4][lane32]
__device__ uint4 g_w2flo[9*2*4*32];           // k2 A frags (lo)

__device__ __forceinline__ uint32_t pack_bf16x2(float e0, float e1) {
    uint32_t r;
    asm("cvt.rn.bf16x2.f32 %0, %1, %2;" : "=r"(r) : "f"(e1), "f"(e0));
    return r;
}
__device__ __forceinline__ float bf16_hi(float v) {
    __nv_bfloat16 hb = __float2bfloat16(v);
    return __bfloat162float(hb);
}
__device__ __forceinline__ void mma_bf16(float* d, const uint32_t* a, uint32_t b0, uint32_t b1) {
    asm volatile(
        "mma.sync.aligned.m16n8k16.row.col.f32.bf16.bf16.f32 "
        "{%0,%1,%2,%3}, {%4,%5,%6,%7}, {%8,%9}, {%0,%1,%2,%3};"
        : "+f"(d[0]), "+f"(d[1]), "+f"(d[2]), "+f"(d[3])
        : "r"(a[0]), "r"(a[1]), "r"(a[2]), "r"(a[3]), "r"(b0), "r"(b1));
}

// ---------------------------------------------------------------------------
// K0: weight prep — pre-packed mma A fragments (hi/lo) for k3 and k2.
// ---------------------------------------------------------------------------
__global__ void k0_wt(const float* __restrict__ rw,
                      const float* __restrict__ off_w,
                      const float* __restrict__ mod_w) {
    int i = blockIdx.x * 256 + threadIdx.x;
    if (i < 9 * 8 * 4 * 32) {
        int kk   = i >> 10;
        int rem  = i & 1023;
        int mt   = rem >> 7;
        int rem2 = rem & 127;
        int ks   = rem2 >> 5;
        int lane = rem2 & 31;
        int g = lane >> 2, t = lane & 3;
        int o0 = mt * 16 + g, o1 = o0 + 8;
        int c0 = ks * 16 + 2 * t, c1 = c0 + 8;

        float w00a = rw[(o0 * 64 + c0) * 9 + kk];
        float w00b = rw[(o0 * 64 + c0 + 1) * 9 + kk];
        float w10a = rw[(o1 * 64 + c0) * 9 + kk];
        float w10b = rw[(o1 * 64 + c0 + 1) * 9 + kk];
        float w01a = rw[(o0 * 64 + c1) * 9 + kk];
        float w01b = rw[(o0 * 64 + c1 + 1) * 9 + kk];
        float w11a = rw[(o1 * 64 + c1) * 9 + kk];
        float w11b = rw[(o1 * 64 + c1 + 1) * 9 + kk];

        float h00a = bf16_hi(w00a), h00b = bf16_hi(w00b);
        float h10a = bf16_hi(w10a), h10b = bf16_hi(w10b);
        float h01a = bf16_hi(w01a), h01b = bf16_hi(w01b);
        float h11a = bf16_hi(w11a), h11b = bf16_hi(w11b);

        uint4 hi, lo;
        hi.x = pack_bf16x2(h00a, h00b);
        hi.y = pack_bf16x2(h10a, h10b);
        hi.z = pack_bf16x2(h01a, h01b);
        hi.w = pack_bf16x2(h11a, h11b);
        lo.x = pack_bf16x2(w00a - h00a, w00b - h00b);
        lo.y = pack_bf16x2(w10a - h10a, w10b - h10b);
        lo.z = pack_bf16x2(w01a - h01a, w01b - h01b);
        lo.w = pack_bf16x2(w11a - h11a, w11b - h11b);
        g_wfhi[i] = hi;
        g_wflo[i] = lo;
    }
    if (i < 9 * 2 * 4 * 32) {
        int lane = i & 31;
        int ks = (i >> 5) & 3;
        int mt = (i >> 7) & 1;
        int kk = i >> 8;
        int g = lane >> 2, t = lane & 3;
        int o0 = mt * 16 + g, o1 = o0 + 8;
        int c0 = ks * 16 + 2 * t, c1 = c0 + 8;

        auto w2v = [&](int o, int c) -> float {
            if (o < 18)      return off_w[(o * 64 + c) * 9 + kk];
            else if (o < 27) return mod_w[((o - 18) * 64 + c) * 9 + kk];
            return 0.f;
        };
        float w00a = w2v(o0, c0), w00b = w2v(o0, c0 + 1);
        float w10a = w2v(o1, c0), w10b = w2v(o1, c0 + 1);
        float w01a = w2v(o0, c1), w01b = w2v(o0, c1 + 1);
        float w11a = w2v(o1, c1), w11b = w2v(o1, c1 + 1);

        float h00a = bf16_hi(w00a), h00b = bf16_hi(w00b);
        float h10a = bf16_hi(w10a), h10b = bf16_hi(w10b);
        float h01a = bf16_hi(w01a), h01b = bf16_hi(w01b);
        float h11a = bf16_hi(w11a), h11b = bf16_hi(w11b);

        uint4 hi, lo;
        hi.x = pack_bf16x2(h00a, h00b);
        hi.y = pack_bf16x2(h10a, h10b);
        hi.z = pack_bf16x2(h01a, h01b);
        hi.w = pack_bf16x2(h11a, h11b);
        lo.x = pack_bf16x2(w00a - h00a, w00b - h00b);
        lo.y = pack_bf16x2(w10a - h10a, w10b - h10b);
        lo.z = pack_bf16x2(w01a - h01a, w01b - h01b);
        lo.w = pack_bf16x2(w11a - h11a, w11b - h11b);
        g_w2fhi[i] = hi;
        g_w2flo[i] = lo;
    }
}

// ---------------------------------------------------------------------------
// K1: 1x1 pre-conv, NCHW in -> NHWC fp32 (g_x2) + NHWC bf16 hi/lo
// ---------------------------------------------------------------------------
__global__ void __launch_bounds__(128) k1_pre(const float* __restrict__ x,
                                              const float* __restrict__ pre_w,
                                              const float* __restrict__ pre_b) {
    __shared__ float wsm[64 * 64];
    __shared__ float bsm[64];
    int tid = threadIdx.x;
    for (int i = tid; i < 4096; i += 128) {
        int co = i & 63, ci = i >> 6;
        wsm[ci * 64 + co] = pre_w[co * 64 + ci];
    }
    if (tid < 64) bsm[tid] = pre_b[tid];
    __syncthreads();

    int bh = blockIdx.x;
    int b = bh >> 7, h = bh & 127;
    int w = tid;

    const float* xp = x + (size_t)b * 64 * NPIX + h * WW + w;
    float xin[64];
#pragma unroll
    for (int ci = 0; ci < 64; ci++) xin[ci] = xp[(size_t)ci * NPIX];

    size_t pbase = ((size_t)bh * WW + w) * 64;
    float4* out4 = (float4*)(g_x2 + pbase);
    const float4* wsm4 = (const float4*)wsm;
    const float4* b4 = (const float4*)bsm;
#pragma unroll
    for (int cog = 0; cog < 16; cog++) {
        float4 acc = b4[cog];
#pragma unroll
        for (int ci = 0; ci < 64; ci++) {
            float4 wv = wsm4[ci * 16 + cog];
            acc.x += xin[ci] * wv.x;
            acc.y += xin[ci] * wv.y;
            acc.z += xin[ci] * wv.z;
            acc.w += xin[ci] * wv.w;
        }
        out4[cog] = acc;
        float h0 = bf16_hi(acc.x), h1 = bf16_hi(acc.y);
        float h2 = bf16_hi(acc.z), h3 = bf16_hi(acc.w);
        uint2 vh = make_uint2(pack_bf16x2(h0, h1), pack_bf16x2(h2, h3));
        uint2 vl = make_uint2(pack_bf16x2(acc.x - h0, acc.y - h1),
                              pack_bf16x2(acc.z - h2, acc.w - h3));
        *(uint2*)(g_xbhi + pbase + cog * 4) = vh;
        *(uint2*)(g_xblo + pbase + cog * 4) = vl;
    }
}

// ---------------------------------------------------------------------------
// K2: offset+mask 3x3 conv via HMMA hi/lo 3-pass.
// Block = one row (128 px), 256 threads / 8 warps. M=32(co pad), N=128, K=576.
// Warp tile: 16 o x 32 px. smem: s_hi/s_lo [128px][72bf16] (stride 144B).
// ---------------------------------------------------------------------------
extern __shared__ float dyn_smem[];
#define S_STRIDE  144   // bytes per px row (72 bf16)

__global__ void __launch_bounds__(256) k2_offmask(const float* __restrict__ off_b,
                                                  const float* __restrict__ mod_b) {
    char* smp = (char*)dyn_smem;
    char* s_hi = smp;
    char* s_lo = smp + 18432;

    int tid = threadIdx.x;
    int warp = tid >> 5, lane = tid & 31;
    int g = lane >> 2, t = lane & 3;
    int bx = blockIdx.x;
    int b = bx >> 7, h = bx & 127;
    size_t pixbase = (size_t)bx * 128;

    int warp_m = warp >> 2;     // 0..1
    int warp_n = warp & 3;      // 0..3

    float acc[4][4];
#pragma unroll
    for (int nt = 0; nt < 4; nt++)
#pragma unroll
        for (int j = 0; j < 4; j++) acc[nt][j] = 0.f;

    for (int kk = 0; kk < 9; kk++) {
        int ky = kk / 3, kx = kk - ky * 3;
        __syncthreads();
        // gather: contiguous row reads (zero pad OOB)
        int y = h - 1 + ky;
        bool yok = (unsigned)y < 128u;
        const __nv_bfloat16* rh = g_xbhi + ((size_t)(b * 128 + (yok ? y : 0)) * 128) * 64;
        const __nv_bfloat16* rl = g_xblo + ((size_t)(b * 128 + (yok ? y : 0)) * 128) * 64;
        for (int i = tid; i < 2048; i += 256) {
            int px = i >> 4, c4 = i & 15;
            int xg = px - 1 + kx;
            uint2 vh = make_uint2(0u, 0u), vl = make_uint2(0u, 0u);
            if (yok && (unsigned)xg < 128u) {
                vh = *(const uint2*)(rh + xg * 64 + c4 * 4);
                vl = *(const uint2*)(rl + xg * 64 + c4 * 4);
            }
            *(uint2*)(s_hi + px * S_STRIDE + c4 * 8) = vh;
            *(uint2*)(s_lo + px * S_STRIDE + c4 * 8) = vl;
        }
        __syncthreads();

        const uint4* wfh = g_w2fhi + (kk * 2 + warp_m) * 4 * 32;
        const uint4* wfl = g_w2flo + (kk * 2 + warp_m) * 4 * 32;
#pragma unroll
        for (int ks = 0; ks < 4; ks++) {
            uint4 ah = __ldg(&wfh[ks * 32 + lane]);
            uint4 al = __ldg(&wfl[ks * 32 + lane]);
            uint32_t bh0[4], bh1[4], bl0[4], bl1[4];
#pragma unroll
            for (int nt = 0; nt < 4; nt++) {
                int npx = warp_n * 32 + nt * 8 + g;
                uint32_t base = (uint32_t)(npx * S_STRIDE + ks * 32 + t * 4);
                bh0[nt] = *(const uint32_t*)(s_hi + base);
                bh1[nt] = *(const uint32_t*)(s_hi + base + 16);
                bl0[nt] = *(const uint32_t*)(s_lo + base);
                bl1[nt] = *(const uint32_t*)(s_lo + base + 16);
            }
#pragma unroll
            for (int nt = 0; nt < 4; nt++) {
                mma_bf16(acc[nt], (const uint32_t*)&ah, bh0[nt], bh1[nt]);
                mma_bf16(acc[nt], (const uint32_t*)&ah, bl0[nt], bl1[nt]);
                mma_bf16(acc[nt], (const uint32_t*)&al, bh0[nt], bh1[nt]);
            }
        }
    }

    // epilogue: bias + sigmoid, scatter to g_offm[pix][32]
    int o0 = warp_m * 16 + g, o1 = o0 + 8;
    auto wr = [&](int o, int px, float v) {
        if (o >= 27) return;
        v += (o < 18) ? __ldg(off_b + o) : __ldg(mod_b + o - 18);
        if (o >= 18) v = 2.0f / (1.0f + expf(-v));
        g_offm[(pixbase + px) * 32 + o] = v;
    };
#pragma unroll
    for (int nt = 0; nt < 4; nt++) {
        int px = warp_n * 32 + nt * 8 + 2 * t;
        wr(o0, px,     acc[nt][0]);
        wr(o0, px + 1, acc[nt][1]);
        wr(o1, px,     acc[nt][2]);
        wr(o1, px + 1, acc[nt][3]);
    }
}
#define K2_SMEM_BYTES 36864

// ---------------------------------------------------------------------------
// K3: deformable sampling + HMMA hi/lo 3-pass, software-pipelined:
// per kk: prefetch gathers for kk+1 into regs while doing MMA on kk.
// Block = half row (64 px), 256 threads / 8 warps, 2 CTAs/SM.
// smem: s_hi[2],s_lo[2] (4x9216=36864) | OSM 36864(8448) | IBUF 45312(9216) | WBUF 54528(9216)
// ---------------------------------------------------------------------------
#define OSM_OFF   36864
#define IBUF_OFF  45312
#define WBUF_OFF  54528
#define K3_SMEM_BYTES 63744

__global__ void __launch_bounds__(256, 2) k3_main(float* __restrict__ out) {
    char* smp = (char*)dyn_smem;

    int tid = threadIdx.x;
    int warp = tid >> 5, lane = tid & 31;
    int g = lane >> 2, t = lane & 3;
    int bx = blockIdx.x;
    int b = bx >> 8;
    int h = (bx >> 1) & 127;
    int seg = bx & 1;
    int w0 = seg * 64;
    size_t pixbase = (((size_t)(b * 128 + h)) * 128 + w0);

    float* osm = (float*)(smp + OSM_OFF);
    int4* ibuf = (int4*)(smp + IBUF_OFF);
    float4* wbuf = (float4*)(smp + WBUF_OFF);

    for (int i = tid; i < 2048; i += 256) {
        int px = i >> 5, j = i & 31;
        osm[px * 33 + j] = g_offm[(pixbase + px) * 32 + j];
    }
    __syncthreads();

    for (int i = tid; i < 9 * 64; i += 256) {
        int kk = i >> 6, px = i & 63;
        int ky = kk / 3, kx = kk - ky * 3;
        float dy = osm[px * 33 + 2 * kk];
        float dx = osm[px * 33 + 2 * kk + 1];
        float m  = osm[px * 33 + 18 + kk];
        float py  = (float)(h - 1 + ky) + dy;
        float pxf = (float)(w0 + px - 1 + kx) + dx;
        float y0f = floorf(py), x0f = floorf(pxf);
        float wy = py - y0f, wx = pxf - x0f;
        int y0 = (int)y0f, x0 = (int)x0f;
        int y1 = y0 + 1, x1 = x0 + 1;
        float w00 = (1.f - wy) * (1.f - wx) * m;
        float w01 = (1.f - wy) * wx * m;
        float w10 = wy * (1.f - wx) * m;
        float w11 = wy * wx * m;
        if ((unsigned)y0 >= 128u) { w00 = 0.f; w01 = 0.f; }
        if ((unsigned)y1 >= 128u) { w10 = 0.f; w11 = 0.f; }
        if ((unsigned)x0 >= 128u) { w00 = 0.f; w10 = 0.f; }
        if ((unsigned)x1 >= 128u) { w01 = 0.f; w11 = 0.f; }
        int yc0 = min(max(y0, 0), 127), yc1 = min(max(y1, 0), 127);
        int xc0 = min(max(x0, 0), 127), xc1 = min(max(x1, 0), 127);
        ibuf[i] = make_int4((yc0 * 128 + xc0) * 64, (yc0 * 128 + xc1) * 64,
                            (yc1 * 128 + xc0) * 64, (yc1 * 128 + xc1) * 64);
        wbuf[i] = make_float4(w00, w01, w10, w11);
    }
    __syncthreads();

    const float* bbase = g_x2 + (size_t)b * NPIX * 64;
    int pxs = lane >> 3;
    int c8  = lane & 7;

    int warp_m = warp >> 1;
    int warp_n = warp & 1;

    float acc[2][4][4];
#pragma unroll
    for (int mt = 0; mt < 2; mt++)
#pragma unroll
        for (int nt = 0; nt < 4; nt++)
#pragma unroll
            for (int j = 0; j < 4; j++) acc[mt][nt][j] = 0.f;

    // gather-prefetch helper state
    auto prefetch = [&](const int4* ib, const float4* wb, int it,
                        float4* r, float4& wtv, uint32_t& by) {
        int half = it & 1;
        int px = (it >> 1) * 4 + pxs;
        int4 off = ib[px];
        wtv = wb[px];
        int c4 = half * 8 + c8;
        r[0] = ((const float4*)(bbase + off.x))[c4];
        r[1] = ((const float4*)(bbase + off.y))[c4];
        r[2] = ((const float4*)(bbase + off.z))[c4];
        r[3] = ((const float4*)(bbase + off.w))[c4];
        by = (uint32_t)(px * S_STRIDE + c4 * 8);
    };
    auto cvst = [&](const float4* r, float4 wtv, uint32_t by, char* dh, char* dl) {
        float v0 = wtv.x * r[0].x + wtv.y * r[1].x + wtv.z * r[2].x + wtv.w * r[3].x;
        float v1 = wtv.x * r[0].y + wtv.y * r[1].y + wtv.z * r[2].y + wtv.w * r[3].y;
        float v2 = wtv.x * r[0].z + wtv.y * r[1].z + wtv.z * r[2].z + wtv.w * r[3].z;
        float v3 = wtv.x * r[0].w + wtv.y * r[1].w + wtv.z * r[2].w + wtv.w * r[3].w;
        float h0 = bf16_hi(v0), h1 = bf16_hi(v1);
        float h2 = bf16_hi(v2), h3 = bf16_hi(v3);
        *(uint2*)(dh + by) = make_uint2(pack_bf16x2(h0, h1), pack_bf16x2(h2, h3));
        *(uint2*)(dl + by) = make_uint2(pack_bf16x2(v0 - h0, v1 - h1),
                                        pack_bf16x2(v2 - h2, v3 - h3));
    };

    // prologue: fill s[0] with kk=0 samples
    {
        float4 r[4]; float4 wtv; uint32_t by;
        for (int it = warp; it < 32; it += 8) {
            prefetch(ibuf, wbuf, it, r, wtv, by);
            cvst(r, wtv, by, smp, smp + 18432);
        }
    }
    __syncthreads();

    for (int kk = 0; kk < 9; kk++) {
        int p = kk & 1;
        char* sh = smp + p * 9216;
        char* sl = smp + 18432 + p * 9216;
        char* nh = smp + (p ^ 1) * 9216;
        char* nl = smp + 18432 + (p ^ 1) * 9216;
        const uint4* wf_hi = g_wfhi + (kk * 8) * 4 * 32;
        const uint4* wf_lo = g_wflo + (kk * 8) * 4 * 32;
        const int4* ib1 = ibuf + (kk + 1) * 64;
        const float4* wb1 = wbuf + (kk + 1) * 64;
        bool pf = (kk < 8);

        float4 ra[2][4]; float4 rw_[2]; uint32_t rby[2];
        if (pf) {
            prefetch(ib1, wb1, warp,     ra[0], rw_[0], rby[0]);
            prefetch(ib1, wb1, warp + 8, ra[1], rw_[1], rby[1]);
        }

        auto do_mma2 = [&](int ks0) {
#pragma unroll
            for (int ks = ks0; ks < ks0 + 2; ks++) {
                uint4 ah0 = __ldg(&wf_hi[((warp_m * 2 + 0) * 4 + ks) * 32 + lane]);
                uint4 ah1 = __ldg(&wf_hi[((warp_m * 2 + 1) * 4 + ks) * 32 + lane]);
                uint32_t bh0[4], bh1[4], bl0[4], bl1[4];
#pragma unroll
                for (int nt = 0; nt < 4; nt++) {
                    int npx = warp_n * 32 + nt * 8 + g;
                    uint32_t base = (uint32_t)(npx * S_STRIDE + ks * 32 + t * 4);
                    bh0[nt] = *(const uint32_t*)(sh + base);
                    bh1[nt] = *(const uint32_t*)(sh + base + 16);
                    bl0[nt] = *(const uint32_t*)(sl + base);
                    bl1[nt] = *(const uint32_t*)(sl + base + 16);
                }
#pragma unroll
                for (int nt = 0; nt < 4; nt++) {
                    mma_bf16(acc[0][nt], (const uint32_t*)&ah0, bh0[nt], bh1[nt]);
                    mma_bf16(acc[1][nt], (const uint32_t*)&ah1, bh0[nt], bh1[nt]);
                    mma_bf16(acc[0][nt], (const uint32_t*)&ah0, bl0[nt], bl1[nt]);
                    mma_bf16(acc[1][nt], (const uint32_t*)&ah1, bl0[nt], bl1[nt]);
                }
                uint4 al0 = __ldg(&wf_lo[((warp_m * 2 + 0) * 4 + ks) * 32 + lane]);
                uint4 al1 = __ldg(&wf_lo[((warp_m * 2 + 1) * 4 + ks) * 32 + lane]);
#pragma unroll
                for (int nt = 0; nt < 4; nt++) {
                    mma_bf16(acc[0][nt], (const uint32_t*)&al0, bh0[nt], bh1[nt]);
                    mma_bf16(acc[1][nt], (const uint32_t*)&al1, bh0[nt], bh1[nt]);
                }
            }
        };

        do_mma2(0);

        if (pf) {
            cvst(ra[0], rw_[0], rby[0], nh, nl);
            cvst(ra[1], rw_[1], rby[1], nh, nl);
            prefetch(ib1, wb1, warp + 16, ra[0], rw_[0], rby[0]);
            prefetch(ib1, wb1, warp + 24, ra[1], rw_[1], rby[1]);
        }

        do_mma2(2);

        if (pf) {
            cvst(ra[0], rw_[0], rby[0], nh, nl);
            cvst(ra[1], rw_[1], rby[1], nh, nl);
        }
        __syncthreads();
    }

    // epilogue: direct STG from C fragments
    float* ob = out + ((size_t)b * COUT) * NPIX + h * WW + w0;
#pragma unroll
    for (int mt = 0; mt < 2; mt++) {
        int o = warp_m * 32 + mt * 16 + g;
#pragma unroll
        for (int nt = 0; nt < 4; nt++) {
            int px = warp_n * 32 + nt * 8 + 2 * t;
            float* p0 = ob + (size_t)o * NPIX + px;
            *(float2*)p0 = make_float2(acc[mt][nt][0], acc[mt][nt][1]);
            float* p1 = p0 + 8 * (size_t)NPIX;
            *(float2*)p1 = make_float2(acc[mt][nt][2], acc[mt][nt][3]);
        }
    }
}

// ---------------------------------------------------------------------------
extern "C" void kernel_launch(void* const* d_in, const int* in_sizes, int n_in,
                              void* d_out, int out_size) {
    const float* x     = (const float*)d_in[0];
    const float* pre_w = (const float*)d_in[1];
    const float* pre_b = (const float*)d_in[2];
    const float* off_w = (const float*)d_in[3];
    const float* off_b = (const float*)d_in[4];
    const float* mod_w = (const float*)d_in[5];
    const float* mod_b = (const float*)d_in[6];
    const float* reg_w = (const float*)d_in[7];
    float* out = (float*)d_out;

    cudaFuncSetAttribute(k2_offmask, cudaFuncAttributeMaxDynamicSharedMemorySize, K2_SMEM_BYTES);
    cudaFuncSetAttribute(k3_main, cudaFuncAttributeMaxDynamicSharedMemorySize, K3_SMEM_BYTES);

    k0_wt<<<36, 256>>>(reg_w, off_w, mod_w);
    k1_pre<<<BB * HH, 128>>>(x, pre_w, pre_b);
    k2_offmask<<<BB * HH, 256, K2_SMEM_BYTES>>>(off_b, mod_b);
    k3_main<<<BB * HH * 2, 256, K3_SMEM_BYTES>>>(out);
}